// round 1
// baseline (speedup 1.0000x reference)
#include <cuda_runtime.h>

#define B_  4
#define S_  2048
#define DM_ 1024
#define H_  16
#define DK_ 64
#define M_  (B_*S_)   // 8192 rows

// Scratch (allocation-free rule: __device__ globals)
__device__ float g_Qh[(size_t)B_*H_*S_*DK_];
__device__ float g_Kh[(size_t)B_*H_*S_*DK_];
__device__ float g_Vh[(size_t)B_*H_*S_*DK_];
__device__ float g_Ctx[(size_t)M_*DM_];

// ---------------------------------------------------------------------------
// Projection GEMM: Y = X @ W^T (+bias). 64x64 tile, BK=16, 256 threads, 4x4/thread.
// headsMode=1: scatter Y into [b][h][s][dk]; headsMode=0: flat [m][n] + bias.
// ---------------------------------------------------------------------------
__global__ __launch_bounds__(256) void proj64(const float* __restrict__ X,
                                              const float* __restrict__ W,
                                              const float* __restrict__ bias,
                                              float* __restrict__ Y,
                                              int headsMode)
{
    __shared__ float As[64][16];   // A natural [m][k]
    __shared__ float Bs[16][64];   // B k-major [k][n]
    const int tid = threadIdx.x;
    const int tx = tid & 15, ty = tid >> 4;
    const int m0 = blockIdx.x * 64, n0 = blockIdx.y * 64;

    float acc[4][4] = {};

    const int lr = tid >> 2;        // 0..63
    const int lk = (tid & 3) * 4;   // 0,4,8,12

    for (int kt = 0; kt < DM_; kt += 16) {
        float4 xa = *(const float4*)&X[(size_t)(m0 + lr) * DM_ + kt + lk];
        float4 wb = *(const float4*)&W[(size_t)(n0 + lr) * DM_ + kt + lk];
        *(float4*)&As[lr][lk] = xa;
        Bs[lk + 0][lr] = wb.x; Bs[lk + 1][lr] = wb.y;
        Bs[lk + 2][lr] = wb.z; Bs[lk + 3][lr] = wb.w;
        __syncthreads();
        #pragma unroll
        for (int k = 0; k < 16; k++) {
            float a0 = As[ty*4 + 0][k];
            float a1 = As[ty*4 + 1][k];
            float a2 = As[ty*4 + 2][k];
            float a3 = As[ty*4 + 3][k];
            float4 b = *(float4*)&Bs[k][tx*4];
            acc[0][0] += a0*b.x; acc[0][1] += a0*b.y; acc[0][2] += a0*b.z; acc[0][3] += a0*b.w;
            acc[1][0] += a1*b.x; acc[1][1] += a1*b.y; acc[1][2] += a1*b.z; acc[1][3] += a1*b.w;
            acc[2][0] += a2*b.x; acc[2][1] += a2*b.y; acc[2][2] += a2*b.z; acc[2][3] += a2*b.w;
            acc[3][0] += a3*b.x; acc[3][1] += a3*b.y; acc[3][2] += a3*b.z; acc[3][3] += a3*b.w;
        }
        __syncthreads();
    }

    if (headsMode) {
        const int h = n0 >> 6;          // one head per 64-wide N tile
        const int dk = tx * 4;
        #pragma unroll
        for (int i = 0; i < 4; i++) {
            int m = m0 + ty*4 + i;
            int b = m >> 11;            // m / S_
            int s = m & (S_ - 1);
            size_t dst = (((size_t)(b*H_ + h) * S_) + s) * DK_ + dk;
            *(float4*)&Y[dst] = make_float4(acc[i][0], acc[i][1], acc[i][2], acc[i][3]);
        }
    } else {
        float4 bb = *(const float4*)&bias[n0 + tx*4];
        #pragma unroll
        for (int i = 0; i < 4; i++) {
            int m = m0 + ty*4 + i;
            *(float4*)&Y[(size_t)m * DM_ + n0 + tx*4] =
                make_float4(acc[i][0] + bb.x, acc[i][1] + bb.y,
                            acc[i][2] + bb.z, acc[i][3] + bb.w);
        }
    }
}

// ---------------------------------------------------------------------------
// Fused attention: per (b,h, 64-query tile). Two passes over K tiles:
//  pass1: online (rowmax m, rowsum l) in registers (shfl reductions)
//  pass2: recompute scores, write normalized probs to d_out, accumulate P@V
// ---------------------------------------------------------------------------
__global__ __launch_bounds__(256) void attn64(const int* __restrict__ mask,
                                              float* __restrict__ attn)
{
    __shared__ float Qs[64][64];    // Q natural [r][d], pre-scaled by 1/8
    __shared__ float KPs[64][64];   // K^T [d][c] in passes; reused as P [r][kk] for PV
    __shared__ float Vs[64][64];    // V natural [kk][d]

    const int tid = threadIdx.x;
    const int tx = tid & 15, ty = tid >> 4;
    const int qt = blockIdx.x, bh = blockIdx.y;
    const int b = bh >> 4, h = bh & 15;

    const float* Qb = g_Qh + (size_t)bh * S_ * DK_ + (size_t)qt * 64 * DK_;
    const float* Kb = g_Kh + (size_t)bh * S_ * DK_;
    const float* Vb = g_Vh + (size_t)bh * S_ * DK_;
    const int*   mb = mask + (size_t)b * S_ * S_ + (size_t)qt * 64 * S_;
    float*       ab = attn + (size_t)bh * S_ * S_ + (size_t)qt * 64 * S_;

    { // load Q tile, apply 1/sqrt(DK)=0.125
        int r = tid >> 4, dq = (tid & 15) * 4;
        #pragma unroll
        for (int ii = 0; ii < 4; ii++) {
            float4 vq = *(const float4*)&Qb[(size_t)(r + ii*16) * DK_ + dq];
            vq.x *= 0.125f; vq.y *= 0.125f; vq.z *= 0.125f; vq.w *= 0.125f;
            *(float4*)&Qs[r + ii*16][dq] = vq;
        }
    }

    float mr[4] = {-1e30f, -1e30f, -1e30f, -1e30f};
    float lr_[4] = {0.f, 0.f, 0.f, 0.f};
    const int lc = tid >> 2;         // key row within tile
    const int lk = (tid & 3) * 4;    // d quarter

    // ---------------- pass 1: softmax statistics ----------------
    for (int kt = 0; kt < 32; kt++) {
        #pragma unroll
        for (int ii = 0; ii < 4; ii++) {
            int d = lk + ii*16;
            float4 vk = *(const float4*)&Kb[(size_t)(kt*64 + lc) * DK_ + d];
            KPs[d + 0][lc] = vk.x; KPs[d + 1][lc] = vk.y;
            KPs[d + 2][lc] = vk.z; KPs[d + 3][lc] = vk.w;
        }
        __syncthreads();

        float sc[4][4] = {};
        #pragma unroll 8
        for (int d = 0; d < 64; d++) {
            float a0 = Qs[ty*4 + 0][d];
            float a1 = Qs[ty*4 + 1][d];
            float a2 = Qs[ty*4 + 2][d];
            float a3 = Qs[ty*4 + 3][d];
            float4 bb4 = *(float4*)&KPs[d][tx*4];
            sc[0][0] += a0*bb4.x; sc[0][1] += a0*bb4.y; sc[0][2] += a0*bb4.z; sc[0][3] += a0*bb4.w;
            sc[1][0] += a1*bb4.x; sc[1][1] += a1*bb4.y; sc[1][2] += a1*bb4.z; sc[1][3] += a1*bb4.w;
            sc[2][0] += a2*bb4.x; sc[2][1] += a2*bb4.y; sc[2][2] += a2*bb4.z; sc[2][3] += a2*bb4.w;
            sc[3][0] += a3*bb4.x; sc[3][1] += a3*bb4.y; sc[3][2] += a3*bb4.z; sc[3][3] += a3*bb4.w;
        }

        #pragma unroll
        for (int i = 0; i < 4; i++) {
            int4 mk = *(const int4*)&mb[(size_t)(ty*4 + i) * S_ + kt*64 + tx*4];
            float s0 = mk.x ? sc[i][0] : -1e9f;
            float s1 = mk.y ? sc[i][1] : -1e9f;
            float s2 = mk.z ? sc[i][2] : -1e9f;
            float s3 = mk.w ? sc[i][3] : -1e9f;
            float tm = fmaxf(fmaxf(s0, s1), fmaxf(s2, s3));
            tm = fmaxf(tm, __shfl_xor_sync(0xffffffffu, tm, 1));
            tm = fmaxf(tm, __shfl_xor_sync(0xffffffffu, tm, 2));
            tm = fmaxf(tm, __shfl_xor_sync(0xffffffffu, tm, 4));
            tm = fmaxf(tm, __shfl_xor_sync(0xffffffffu, tm, 8));
            float nm = fmaxf(mr[i], tm);
            float ts = __expf(s0 - nm) + __expf(s1 - nm) + __expf(s2 - nm) + __expf(s3 - nm);
            ts += __shfl_xor_sync(0xffffffffu, ts, 1);
            ts += __shfl_xor_sync(0xffffffffu, ts, 2);
            ts += __shfl_xor_sync(0xffffffffu, ts, 4);
            ts += __shfl_xor_sync(0xffffffffu, ts, 8);
            lr_[i] = lr_[i] * __expf(mr[i] - nm) + ts;
            mr[i] = nm;
        }
        __syncthreads();
    }

    float invl[4];
    #pragma unroll
    for (int i = 0; i < 4; i++) invl[i] = 1.0f / lr_[i];

    float cacc[4][4] = {};

    // ---------------- pass 2: probs write + P@V ----------------
    for (int kt = 0; kt < 32; kt++) {
        #pragma unroll
        for (int ii = 0; ii < 4; ii++) {
            int d = lk + ii*16;
            float4 vk = *(const float4*)&Kb[(size_t)(kt*64 + lc) * DK_ + d];
            KPs[d + 0][lc] = vk.x; KPs[d + 1][lc] = vk.y;
            KPs[d + 2][lc] = vk.z; KPs[d + 3][lc] = vk.w;
        }
        {
            int r = tid >> 4, dq = (tid & 15) * 4;
            #pragma unroll
            for (int ii = 0; ii < 4; ii++)
                *(float4*)&Vs[r + ii*16][dq] =
                    *(const float4*)&Vb[(size_t)(kt*64 + r + ii*16) * DK_ + dq];
        }
        __syncthreads();

        float sc[4][4] = {};
        #pragma unroll 8
        for (int d = 0; d < 64; d++) {
            float a0 = Qs[ty*4 + 0][d];
            float a1 = Qs[ty*4 + 1][d];
            float a2 = Qs[ty*4 + 2][d];
            float a3 = Qs[ty*4 + 3][d];
            float4 bb4 = *(float4*)&KPs[d][tx*4];
            sc[0][0] += a0*bb4.x; sc[0][1] += a0*bb4.y; sc[0][2] += a0*bb4.z; sc[0][3] += a0*bb4.w;
            sc[1][0] += a1*bb4.x; sc[1][1] += a1*bb4.y; sc[1][2] += a1*bb4.z; sc[1][3] += a1*bb4.w;
            sc[2][0] += a2*bb4.x; sc[2][1] += a2*bb4.y; sc[2][2] += a2*bb4.z; sc[2][3] += a2*bb4.w;
            sc[3][0] += a3*bb4.x; sc[3][1] += a3*bb4.y; sc[3][2] += a3*bb4.z; sc[3][3] += a3*bb4.w;
        }

        #pragma unroll
        for (int i = 0; i < 4; i++) {
            int4 mk = *(const int4*)&mb[(size_t)(ty*4 + i) * S_ + kt*64 + tx*4];
            float p0 = __expf((mk.x ? sc[i][0] : -1e9f) - mr[i]) * invl[i];
            float p1 = __expf((mk.y ? sc[i][1] : -1e9f) - mr[i]) * invl[i];
            float p2 = __expf((mk.z ? sc[i][2] : -1e9f) - mr[i]) * invl[i];
            float p3 = __expf((mk.w ? sc[i][3] : -1e9f) - mr[i]) * invl[i];
            *(float4*)&ab[(size_t)(ty*4 + i) * S_ + kt*64 + tx*4] = make_float4(p0, p1, p2, p3);
            sc[i][0] = p0; sc[i][1] = p1; sc[i][2] = p2; sc[i][3] = p3;
        }
        __syncthreads();  // done reading K^T, safe to overwrite with P

        #pragma unroll
        for (int i = 0; i < 4; i++)
            *(float4*)&KPs[ty*4 + i][tx*4] =
                make_float4(sc[i][0], sc[i][1], sc[i][2], sc[i][3]);
        __syncthreads();

        #pragma unroll 8
        for (int kk = 0; kk < 64; kk++) {
            float a0 = KPs[ty*4 + 0][kk];
            float a1 = KPs[ty*4 + 1][kk];
            float a2 = KPs[ty*4 + 2][kk];
            float a3 = KPs[ty*4 + 3][kk];
            float4 vv = *(float4*)&Vs[kk][tx*4];
            cacc[0][0] += a0*vv.x; cacc[0][1] += a0*vv.y; cacc[0][2] += a0*vv.z; cacc[0][3] += a0*vv.w;
            cacc[1][0] += a1*vv.x; cacc[1][1] += a1*vv.y; cacc[1][2] += a1*vv.z; cacc[1][3] += a1*vv.w;
            cacc[2][0] += a2*vv.x; cacc[2][1] += a2*vv.y; cacc[2][2] += a2*vv.z; cacc[2][3] += a2*vv.w;
            cacc[3][0] += a3*vv.x; cacc[3][1] += a3*vv.y; cacc[3][2] += a3*vv.z; cacc[3][3] += a3*vv.w;
        }
        __syncthreads();
    }

    // write context, already permuted to [b][s][h*DK+dk]
    #pragma unroll
    for (int i = 0; i < 4; i++) {
        int qrow = qt*64 + ty*4 + i;
        size_t dst = ((size_t)(b * S_ + qrow)) * DM_ + h * DK_ + tx*4;
        *(float4*)&g_Ctx[dst] = make_float4(cacc[i][0], cacc[i][1], cacc[i][2], cacc[i][3]);
    }
}

// ---------------------------------------------------------------------------
extern "C" void kernel_launch(void* const* d_in, const int* in_sizes, int n_in,
                              void* d_out, int out_size)
{
    const float* q    = (const float*)d_in[0];
    const float* k    = (const float*)d_in[1];
    const float* v    = (const float*)d_in[2];
    const int*   mask = (const int*)  d_in[3];
    const float* Wq   = (const float*)d_in[4];
    const float* Wk   = (const float*)d_in[5];
    const float* Wv   = (const float*)d_in[6];
    const float* Wo   = (const float*)d_in[7];
    const float* bo   = (const float*)d_in[8];

    float* out      = (float*)d_out;
    float* ctx_out  = out;                             // [B,S,DM]
    float* attn_out = out + (size_t)B_ * S_ * DM_;     // [B,H,S,S]

    void *pQ, *pK, *pV, *pC;
    cudaGetSymbolAddress(&pQ, g_Qh);
    cudaGetSymbolAddress(&pK, g_Kh);
    cudaGetSymbolAddress(&pV, g_Vh);
    cudaGetSymbolAddress(&pC, g_Ctx);

    dim3 gproj(M_/64, DM_/64);
    proj64<<<gproj, 256>>>(q, Wq, nullptr, (float*)pQ, 1);
    proj64<<<gproj, 256>>>(k, Wk, nullptr, (float*)pK, 1);
    proj64<<<gproj, 256>>>(v, Wv, nullptr, (float*)pV, 1);

    attn64<<<dim3(S_/64, B_*H_), 256>>>(mask, attn_out);

    proj64<<<gproj, 256>>>((const float*)pC, Wo, bo, ctx_out, 0);
}

// round 2
// speedup vs baseline: 1.2086x; 1.2086x over previous
#include <cuda_runtime.h>

#define B_  4
#define S_  2048
#define DM_ 1024
#define H_  16
#define DK_ 64
#define M_  (B_*S_)   // 8192 rows

// Scratch (allocation-free rule: __device__ globals)
__device__ float g_Qh[(size_t)B_*H_*S_*DK_];
__device__ float g_Kh[(size_t)B_*H_*S_*DK_];
__device__ float g_Vh[(size_t)B_*H_*S_*DK_];
__device__ float g_Ctx[(size_t)M_*DM_];
__device__ float g_invl[(size_t)B_*H_*S_];

// ---------------------------------------------------------------------------
// Projection GEMM: Y = X @ W^T (+bias). Tile 256m x 128n, BK=16, 256 threads,
// 16x8 per thread (rows ry+16*i). headsMode=1 scatters into [b][h][s][dk].
// ---------------------------------------------------------------------------
__global__ __launch_bounds__(256) void proj2(const float* __restrict__ X,
                                             const float* __restrict__ W,
                                             const float* __restrict__ bias,
                                             float* __restrict__ Y,
                                             int headsMode)
{
    __shared__ float Xs[16][256];
    __shared__ float Ws[16][128];
    const int tid = threadIdx.x;
    const int tx = tid & 15;           // n-group: cols tx*8 .. +7
    const int ry = tid >> 4;           // row base: rows ry + 16*i
    const int m0 = blockIdx.x * 256, n0 = blockIdx.y * 128;

    float acc[16][8];
    #pragma unroll
    for (int i = 0; i < 16; i++)
        #pragma unroll
        for (int j = 0; j < 8; j++) acc[i][j] = 0.f;

    const int wr = tid & 127;          // W row
    const int wh = (tid >> 7) * 8;     // W k-half

    float4 px[4], pw[2];
    {
        const float* Xp = X + (size_t)(m0 + tid) * DM_;
        #pragma unroll
        for (int j = 0; j < 4; j++) px[j] = *(const float4*)(Xp + j*4);
        const float* Wp = W + (size_t)(n0 + wr) * DM_ + wh;
        pw[0] = *(const float4*)(Wp);
        pw[1] = *(const float4*)(Wp + 4);
    }

    for (int kt = 0; kt < DM_; kt += 16) {
        #pragma unroll
        for (int j = 0; j < 4; j++) {
            Xs[j*4+0][tid] = px[j].x; Xs[j*4+1][tid] = px[j].y;
            Xs[j*4+2][tid] = px[j].z; Xs[j*4+3][tid] = px[j].w;
        }
        #pragma unroll
        for (int j = 0; j < 2; j++) {
            Ws[wh+j*4+0][wr] = pw[j].x; Ws[wh+j*4+1][wr] = pw[j].y;
            Ws[wh+j*4+2][wr] = pw[j].z; Ws[wh+j*4+3][wr] = pw[j].w;
        }
        __syncthreads();

        if (kt + 16 < DM_) {
            const float* Xp = X + (size_t)(m0 + tid) * DM_ + kt + 16;
            #pragma unroll
            for (int j = 0; j < 4; j++) px[j] = *(const float4*)(Xp + j*4);
            const float* Wp = W + (size_t)(n0 + wr) * DM_ + kt + 16 + wh;
            pw[0] = *(const float4*)(Wp);
            pw[1] = *(const float4*)(Wp + 4);
        }

        #pragma unroll
        for (int k = 0; k < 16; k++) {
            float bf[8];
            *(float4*)&bf[0] = *(float4*)&Ws[k][tx*8];
            *(float4*)&bf[4] = *(float4*)&Ws[k][tx*8 + 4];
            float af[16];
            #pragma unroll
            for (int i = 0; i < 16; i++) af[i] = Xs[k][ry + 16*i];
            #pragma unroll
            for (int i = 0; i < 16; i++)
                #pragma unroll
                for (int j = 0; j < 8; j++)
                    acc[i][j] += af[i] * bf[j];
        }
        __syncthreads();
    }

    if (headsMode) {
        #pragma unroll
        for (int i = 0; i < 16; i++) {
            int m = m0 + ry + 16*i;
            int b = m >> 11, s = m & (S_ - 1);
            #pragma unroll
            for (int j4 = 0; j4 < 8; j4 += 4) {
                int n = n0 + tx*8 + j4;
                int h = n >> 6, dk = n & 63;
                size_t dst = (((size_t)(b*H_ + h) * S_) + s) * DK_ + dk;
                *(float4*)&Y[dst] = make_float4(acc[i][j4], acc[i][j4+1],
                                                acc[i][j4+2], acc[i][j4+3]);
            }
        }
    } else {
        float bb[8];
        *(float4*)&bb[0] = *(const float4*)&bias[n0 + tx*8];
        *(float4*)&bb[4] = *(const float4*)&bias[n0 + tx*8 + 4];
        #pragma unroll
        for (int i = 0; i < 16; i++) {
            int m = m0 + ry + 16*i;
            #pragma unroll
            for (int j4 = 0; j4 < 8; j4 += 4) {
                *(float4*)&Y[(size_t)m * DM_ + n0 + tx*8 + j4] =
                    make_float4(acc[i][j4]+bb[j4], acc[i][j4+1]+bb[j4+1],
                                acc[i][j4+2]+bb[j4+2], acc[i][j4+3]+bb[j4+3]);
            }
        }
    }
}

// ---------------------------------------------------------------------------
// Fused single-pass attention. Tile: 128 queries x 128 keys, 256 threads.
// No running max (scores bounded); writes unnormalized exp(s) to attn output,
// accumulates unnormalized PV, scales context by 1/l at the end. attn output
// is normalized by a follow-up rescale kernel using g_invl.
// ---------------------------------------------------------------------------
#define PS_STRIDE 132
#define VS_STRIDE 68
// floats: Qt[64][128] | KT[64][128] | Vs[128][68] | Ps[128][132]
#define SM_KT   8192
#define SM_VS   16384
#define SM_PS   (16384 + 128*VS_STRIDE)
#define SM_FLOATS (SM_PS + 128*PS_STRIDE)

__global__ __launch_bounds__(256) void attn2(const int* __restrict__ mask,
                                             float* __restrict__ attn)
{
    extern __shared__ float sm[];
    float* Qt = sm;             // [d][q]
    float* KT = sm + SM_KT;     // [d][kk]
    float* Vs = sm + SM_VS;     // [kk][d] stride 68
    float* Ps = sm + SM_PS;     // [q][col'] stride 132, rotated groups
    float* Cred = sm;           // reuse Qt/KT region: [q][d] stride 68
    __shared__ float sInvl[128];

    const int tid = threadIdx.x;
    const int qt = blockIdx.x, bh = blockIdx.y;
    const int b = bh >> 4, h = bh & 15;

    const float* Qb = g_Qh + ((size_t)bh * S_ + qt*128) * DK_;
    const float* Kb = g_Kh + (size_t)bh * S_ * DK_;
    const float* Vb = g_Vh + (size_t)bh * S_ * DK_;
    const int*   mb = mask + (size_t)b * S_ * S_ + (size_t)qt * 128 * S_;
    float*       ab = attn + (size_t)bh * S_ * S_ + (size_t)qt * 128 * S_;

    const int sx = tid & 15, sy = tid >> 4;        // score map: rows sy*8+i, cols sx*8+j
    const int half = tid >> 7, t2 = tid & 127;     // PV map
    const int py = t2 & 15, px = t2 >> 4;          // rows py+16i, cols px*8+j

    // Load Q transposed and pre-scaled by 1/sqrt(64)
    {
        const int qr = tid & 127, dh = (tid >> 7) * 32;
        const float* qp = Qb + (size_t)qr * DK_ + dh;
        #pragma unroll
        for (int j = 0; j < 8; j++) {
            float4 v = *(const float4*)(qp + j*4);
            int d = dh + j*4;
            Qt[(d+0)*128 + qr] = v.x * 0.125f;
            Qt[(d+1)*128 + qr] = v.y * 0.125f;
            Qt[(d+2)*128 + qr] = v.z * 0.125f;
            Qt[(d+3)*128 + qr] = v.w * 0.125f;
        }
    }

    float l[8];
    #pragma unroll
    for (int i = 0; i < 8; i++) l[i] = 0.f;
    float cacc[8][8];
    #pragma unroll
    for (int i = 0; i < 8; i++)
        #pragma unroll
        for (int j = 0; j < 8; j++) cacc[i][j] = 0.f;

    for (int kt = 0; kt < 16; kt++) {
        { // K tile -> KT (transposed)
            const int kr = tid & 127, dh = (tid >> 7) * 32;
            const float* kp = Kb + (size_t)(kt*128 + kr) * DK_ + dh;
            #pragma unroll
            for (int j = 0; j < 8; j++) {
                float4 v = *(const float4*)(kp + j*4);
                int d = dh + j*4;
                KT[(d+0)*128 + kr] = v.x; KT[(d+1)*128 + kr] = v.y;
                KT[(d+2)*128 + kr] = v.z; KT[(d+3)*128 + kr] = v.w;
            }
        }
        { // V tile -> Vs (natural, padded stride)
            const int vr = tid >> 1, dh = (tid & 1) * 32;
            const float* vp = Vb + (size_t)(kt*128 + vr) * DK_ + dh;
            #pragma unroll
            for (int j = 0; j < 8; j++)
                *(float4*)&Vs[vr*VS_STRIDE + dh + j*4] = *(const float4*)(vp + j*4);
        }
        // mask prefetch (8 bits per row), hidden under sync + score FMA
        unsigned mbits[8];
        #pragma unroll
        for (int i = 0; i < 8; i++) {
            const int* mp = mb + (size_t)(sy*8 + i) * S_ + kt*128 + sx*8;
            int4 m0 = *(const int4*)mp;
            int4 m1 = *(const int4*)(mp + 4);
            mbits[i] = (unsigned)(m0.x != 0)       | ((unsigned)(m0.y != 0) << 1)
                     | ((unsigned)(m0.z != 0) << 2) | ((unsigned)(m0.w != 0) << 3)
                     | ((unsigned)(m1.x != 0) << 4) | ((unsigned)(m1.y != 0) << 5)
                     | ((unsigned)(m1.z != 0) << 6) | ((unsigned)(m1.w != 0) << 7);
        }
        __syncthreads();

        // scores: acc[8][8] = Q[sy*8..][:] . K[sx*8..][:]
        float acc[8][8];
        #pragma unroll
        for (int i = 0; i < 8; i++)
            #pragma unroll
            for (int j = 0; j < 8; j++) acc[i][j] = 0.f;

        #pragma unroll 8
        for (int d = 0; d < 64; d++) {
            float af[8], bf[8];
            *(float4*)&af[0] = *(float4*)&Qt[d*128 + sy*8];
            *(float4*)&af[4] = *(float4*)&Qt[d*128 + sy*8 + 4];
            *(float4*)&bf[0] = *(float4*)&KT[d*128 + sx*8];
            *(float4*)&bf[4] = *(float4*)&KT[d*128 + sx*8 + 4];
            #pragma unroll
            for (int i = 0; i < 8; i++)
                #pragma unroll
                for (int j = 0; j < 8; j++)
                    acc[i][j] += af[i] * bf[j];
        }

        // exp + mask, write unnormalized probs to smem (rotated) and global
        #pragma unroll
        for (int i = 0; i < 8; i++) {
            int r = sy*8 + i;
            unsigned mbw = mbits[i];
            float p[8];
            #pragma unroll
            for (int j = 0; j < 8; j++)
                p[j] = (mbw >> j & 1u) ? __expf(acc[i][j]) : 0.f;
            l[i] += ((p[0]+p[1]) + (p[2]+p[3])) + ((p[4]+p[5]) + (p[6]+p[7]));
            int cg = ((sx + r) & 15) * 8;
            *(float4*)&Ps[r*PS_STRIDE + cg]     = *(float4*)&p[0];
            *(float4*)&Ps[r*PS_STRIDE + cg + 4] = *(float4*)&p[4];
            *(float4*)&ab[(size_t)r * S_ + kt*128 + sx*8]     = *(float4*)&p[0];
            *(float4*)&ab[(size_t)r * S_ + kt*128 + sx*8 + 4] = *(float4*)&p[4];
        }
        __syncthreads();

        // PV: each half covers 64 keys of this tile
        #pragma unroll 2
        for (int step = 0; step < 16; step++) {
            int kkb = half*64 + step*4;
            int g = kkb >> 3, o = kkb & 7;
            float a_s[8][4];
            #pragma unroll
            for (int i = 0; i < 8; i++) {
                int r = py + 16*i;
                *(float4*)a_s[i] = *(float4*)&Ps[r*PS_STRIDE + ((g + r) & 15)*8 + o];
            }
            #pragma unroll
            for (int c = 0; c < 4; c++) {
                float bf[8];
                *(float4*)&bf[0] = *(float4*)&Vs[(kkb+c)*VS_STRIDE + px*8];
                *(float4*)&bf[4] = *(float4*)&Vs[(kkb+c)*VS_STRIDE + px*8 + 4];
                #pragma unroll
                for (int i = 0; i < 8; i++) {
                    float av = a_s[i][c];
                    #pragma unroll
                    for (int j = 0; j < 8; j++)
                        cacc[i][j] += av * bf[j];
                }
            }
        }
        __syncthreads();
    }

    // row-sum reduce across the 16-lane sx group, publish 1/l
    #pragma unroll
    for (int i = 0; i < 8; i++) {
        float s = l[i];
        s += __shfl_xor_sync(0xffffffffu, s, 1);
        s += __shfl_xor_sync(0xffffffffu, s, 2);
        s += __shfl_xor_sync(0xffffffffu, s, 4);
        s += __shfl_xor_sync(0xffffffffu, s, 8);
        l[i] = 1.0f / s;
    }
    if (sx == 0) {
        #pragma unroll
        for (int i = 0; i < 8; i++) {
            sInvl[sy*8 + i] = l[i];
            g_invl[(size_t)bh * S_ + qt*128 + sy*8 + i] = l[i];
        }
    }
    __syncthreads();

    // cross-half reduction of PV partials, scale by 1/l, write context
    if (half == 1) {
        #pragma unroll
        for (int i = 0; i < 8; i++) {
            int r = py + 16*i;
            *(float4*)&Cred[r*VS_STRIDE + px*8]     = *(float4*)&cacc[i][0];
            *(float4*)&Cred[r*VS_STRIDE + px*8 + 4] = *(float4*)&cacc[i][4];
        }
    }
    __syncthreads();
    if (half == 0) {
        #pragma unroll
        for (int i = 0; i < 8; i++) {
            int r = py + 16*i;
            float sc = sInvl[r];
            float o[8];
            *(float4*)&o[0] = *(float4*)&Cred[r*VS_STRIDE + px*8];
            *(float4*)&o[4] = *(float4*)&Cred[r*VS_STRIDE + px*8 + 4];
            #pragma unroll
            for (int j = 0; j < 8; j++) o[j] = (o[j] + cacc[i][j]) * sc;
            size_t dst = ((size_t)(b * S_ + qt*128 + r)) * DM_ + h*DK_ + px*8;
            *(float4*)&g_Ctx[dst]     = *(float4*)&o[0];
            *(float4*)&g_Ctx[dst + 4] = *(float4*)&o[4];
        }
    }
}

// ---------------------------------------------------------------------------
// Normalize attention rows: attn[row][:] *= invl[row]
// ---------------------------------------------------------------------------
__global__ __launch_bounds__(256) void rescale(float* __restrict__ attn)
{
    const int row = blockIdx.x;
    const float s = g_invl[row];
    float4* p = (float4*)(attn + (size_t)row * S_);
    const int t = threadIdx.x;
    float4 v0 = p[t], v1 = p[t + 256];
    v0.x *= s; v0.y *= s; v0.z *= s; v0.w *= s;
    v1.x *= s; v1.y *= s; v1.z *= s; v1.w *= s;
    p[t] = v0; p[t + 256] = v1;
}

// ---------------------------------------------------------------------------
extern "C" void kernel_launch(void* const* d_in, const int* in_sizes, int n_in,
                              void* d_out, int out_size)
{
    const float* q    = (const float*)d_in[0];
    const float* k    = (const float*)d_in[1];
    const float* v    = (const float*)d_in[2];
    const int*   mask = (const int*)  d_in[3];
    const float* Wq   = (const float*)d_in[4];
    const float* Wk   = (const float*)d_in[5];
    const float* Wv   = (const float*)d_in[6];
    const float* Wo   = (const float*)d_in[7];
    const float* bo   = (const float*)d_in[8];

    float* out      = (float*)d_out;
    float* ctx_out  = out;                             // [B,S,DM]
    float* attn_out = out + (size_t)B_ * S_ * DM_;     // [B,H,S,S]

    void *pQ, *pK, *pV, *pC;
    cudaGetSymbolAddress(&pQ, g_Qh);
    cudaGetSymbolAddress(&pK, g_Kh);
    cudaGetSymbolAddress(&pV, g_Vh);
    cudaGetSymbolAddress(&pC, g_Ctx);

    const int smemBytes = SM_FLOATS * 4;
    cudaFuncSetAttribute(attn2, cudaFuncAttributeMaxDynamicSharedMemorySize, smemBytes);

    dim3 gproj(M_/256, DM_/128);
    proj2<<<gproj, 256>>>(q, Wq, nullptr, (float*)pQ, 1);
    proj2<<<gproj, 256>>>(k, Wk, nullptr, (float*)pK, 1);
    proj2<<<gproj, 256>>>(v, Wv, nullptr, (float*)pV, 1);

    attn2<<<dim3(S_/128, B_*H_), 256, smemBytes>>>(mask, attn_out);

    rescale<<<B_*H_*S_, 256>>>(attn_out);

    proj2<<<gproj, 256>>>((const float*)pC, Wo, bo, ctx_out, 0);
}

// round 3
// speedup vs baseline: 2.3033x; 1.9058x over previous
#include <cuda_runtime.h>

#define B_  4
#define S_  2048
#define DM_ 1024
#define H_  16
#define DK_ 64
#define M_  (B_*S_)   // 8192 rows

// Scratch (allocation-free rule: __device__ globals)
__device__ float g_Qh[(size_t)B_*H_*S_*DK_];
__device__ float g_Kh[(size_t)B_*H_*S_*DK_];
__device__ float g_Vh[(size_t)B_*H_*S_*DK_];
__device__ float g_Ctx[(size_t)M_*DM_];
__device__ float g_invl[(size_t)B_*H_*S_];

// ---------------------------------------------------------------------------
// helpers: tf32 convert (round-to-nearest) + m16n8k8 tf32 mma
// ---------------------------------------------------------------------------
__device__ __forceinline__ unsigned f2tf(float x) {
    unsigned u;
    asm("cvt.rna.tf32.f32 %0, %1;" : "=r"(u) : "f"(x));
    return u;
}
__device__ __forceinline__ void mma_tf32(float c[4],
                                         unsigned a0, unsigned a1, unsigned a2, unsigned a3,
                                         unsigned b0, unsigned b1) {
    asm("mma.sync.aligned.m16n8k8.row.col.f32.tf32.tf32.f32 "
        "{%0,%1,%2,%3},{%4,%5,%6,%7},{%8,%9},{%0,%1,%2,%3};"
        : "+f"(c[0]), "+f"(c[1]), "+f"(c[2]), "+f"(c[3])
        : "r"(a0), "r"(a1), "r"(a2), "r"(a3), "r"(b0), "r"(b1));
}

// ---------------------------------------------------------------------------
// Projection GEMM (tf32 mma): Y = X @ W^T (+bias). Tile 128m x 128n, BK=32,
// 8 warps as 2(m)x4(n); warp = 64m x 32n = 4x4 m16n8k8 frags.
// headsMode=1 scatters into [b][h][s][dk]; else flat + bias.
// ---------------------------------------------------------------------------
#define XSTR 36
__global__ __launch_bounds__(256) void proj_mma(const float* __restrict__ X,
                                                const float* __restrict__ W,
                                                const float* __restrict__ bias,
                                                float* __restrict__ Y,
                                                int headsMode)
{
    __shared__ unsigned Xs[128 * XSTR];
    __shared__ unsigned Ws[128 * XSTR];
    const int tid = threadIdx.x;
    const int lane = tid & 31, wid = tid >> 5;
    const int wm = wid >> 2, wn = wid & 3;
    const int gr = lane >> 2, tg = lane & 3;
    const int m0 = blockIdx.x * 128, n0 = blockIdx.y * 128;

    const int lr = tid >> 1;          // 0..127 (row)
    const int lh = (tid & 1) * 16;    // k-half

    float c[4][4][4];
    #pragma unroll
    for (int mi = 0; mi < 4; mi++)
        #pragma unroll
        for (int ni = 0; ni < 4; ni++)
            #pragma unroll
            for (int r = 0; r < 4; r++) c[mi][ni][r] = 0.f;

    float4 px[4], pw[4];
    {
        const float* Xp = X + (size_t)(m0 + lr) * DM_ + lh;
        const float* Wp = W + (size_t)(n0 + lr) * DM_ + lh;
        #pragma unroll
        for (int j = 0; j < 4; j++) { px[j] = *(const float4*)(Xp + 4*j); pw[j] = *(const float4*)(Wp + 4*j); }
    }

    for (int kt = 0; kt < DM_; kt += 32) {
        #pragma unroll
        for (int j = 0; j < 4; j++) {
            uint4 ux = make_uint4(f2tf(px[j].x), f2tf(px[j].y), f2tf(px[j].z), f2tf(px[j].w));
            uint4 uw = make_uint4(f2tf(pw[j].x), f2tf(pw[j].y), f2tf(pw[j].z), f2tf(pw[j].w));
            *(uint4*)&Xs[lr * XSTR + lh + 4*j] = ux;
            *(uint4*)&Ws[lr * XSTR + lh + 4*j] = uw;
        }
        __syncthreads();

        if (kt + 32 < DM_) {
            const float* Xp = X + (size_t)(m0 + lr) * DM_ + kt + 32 + lh;
            const float* Wp = W + (size_t)(n0 + lr) * DM_ + kt + 32 + lh;
            #pragma unroll
            for (int j = 0; j < 4; j++) { px[j] = *(const float4*)(Xp + 4*j); pw[j] = *(const float4*)(Wp + 4*j); }
        }

        #pragma unroll
        for (int kc = 0; kc < 4; kc++) {
            unsigned a[4][4], bb[4][2];
            const int ab0 = (wm*64 + gr) * XSTR + kc*8 + tg;
            #pragma unroll
            for (int mi = 0; mi < 4; mi++) {
                a[mi][0] = Xs[ab0 + (mi*16    ) * XSTR];
                a[mi][1] = Xs[ab0 + (mi*16 + 8) * XSTR];
                a[mi][2] = Xs[ab0 + (mi*16    ) * XSTR + 4];
                a[mi][3] = Xs[ab0 + (mi*16 + 8) * XSTR + 4];
            }
            const int bb0 = (wn*32 + gr) * XSTR + kc*8 + tg;
            #pragma unroll
            for (int ni = 0; ni < 4; ni++) {
                bb[ni][0] = Ws[bb0 + ni*8 * XSTR];
                bb[ni][1] = Ws[bb0 + ni*8 * XSTR + 4];
            }
            #pragma unroll
            for (int mi = 0; mi < 4; mi++)
                #pragma unroll
                for (int ni = 0; ni < 4; ni++)
                    mma_tf32(c[mi][ni], a[mi][0], a[mi][1], a[mi][2], a[mi][3],
                             bb[ni][0], bb[ni][1]);
        }
        __syncthreads();
    }

    if (headsMode) {
        #pragma unroll
        for (int mi = 0; mi < 4; mi++) {
            int m = m0 + wm*64 + mi*16 + gr;
            int b = m >> 11, s = m & (S_ - 1);
            #pragma unroll
            for (int ni = 0; ni < 4; ni++) {
                int n = n0 + wn*32 + ni*8 + 2*tg;
                int h = n >> 6, dk = n & 63;
                size_t base = (((size_t)(b*H_ + h) * S_) + s) * DK_ + dk;
                *(float2*)&Y[base]            = make_float2(c[mi][ni][0], c[mi][ni][1]);
                *(float2*)&Y[base + 8*DK_]    = make_float2(c[mi][ni][2], c[mi][ni][3]);
            }
        }
    } else {
        #pragma unroll
        for (int mi = 0; mi < 4; mi++) {
            int m = m0 + wm*64 + mi*16 + gr;
            #pragma unroll
            for (int ni = 0; ni < 4; ni++) {
                int n = n0 + wn*32 + ni*8 + 2*tg;
                float b0 = bias[n], b1 = bias[n+1];
                *(float2*)&Y[(size_t)m * DM_ + n] =
                    make_float2(c[mi][ni][0] + b0, c[mi][ni][1] + b1);
                *(float2*)&Y[(size_t)(m+8) * DM_ + n] =
                    make_float2(c[mi][ni][2] + b0, c[mi][ni][3] + b1);
            }
        }
    }
}

// ---------------------------------------------------------------------------
// Fused attention (tf32 mma). CTA: 128 queries, loops 16 key-tiles of 128.
// Scores via mma (warp=64x32), exp+mask SIMT on fragments, unnormalized probs
// to global + smem(tf32); PV via mma (warp=64m x 16n, k=128). Context scaled
// by 1/l in-kernel; attention normalized by rescale kernel.
// smem words: Qs 128*68 | Ks 128*68 | Vs 128*68 | Ps 128*132 | rowSum 128
// ---------------------------------------------------------------------------
#define QSTR 68
#define PSTR2 132
#define OFF_KS 8704
#define OFF_VS 17408
#define OFF_PS 26112
#define OFF_RS 43008
#define SM_WORDS 43136

__global__ __launch_bounds__(256) void attn_mma(const int* __restrict__ mask,
                                                float* __restrict__ attn)
{
    extern __shared__ unsigned smu[];
    unsigned* Qs = smu;
    unsigned* Ks = smu + OFF_KS;
    unsigned* Vs = smu + OFF_VS;
    unsigned* Ps = smu + OFF_PS;
    float* rowSum = (float*)(smu + OFF_RS);

    const int tid = threadIdx.x;
    const int lane = tid & 31, wid = tid >> 5;
    const int wm = wid >> 2, wn = wid & 3;
    const int gr = lane >> 2, tg = lane & 3;
    const int qt = blockIdx.x, bh = blockIdx.y;
    const int b = bh >> 4, h = bh & 15;

    const float* Qb = g_Qh + ((size_t)bh * S_ + qt*128) * DK_;
    const float* Kb = g_Kh + (size_t)bh * S_ * DK_;
    const float* Vb = g_Vh + (size_t)bh * S_ * DK_;
    const int*   mb = mask + (size_t)b * S_ * S_ + (size_t)qt * 128 * S_;
    float*       ab = attn + (size_t)bh * S_ * S_ + (size_t)qt * 128 * S_;

    if (tid < 128) rowSum[tid] = 0.f;

    const int lr = tid >> 1;            // 0..127
    const int lh2 = (tid & 1) * 32;     // d-half
    { // Q load: scale by 1/sqrt(64), tf32 round
        const float* qp = Qb + (size_t)lr * DK_ + lh2;
        #pragma unroll
        for (int j = 0; j < 8; j++) {
            float4 v = *(const float4*)(qp + 4*j);
            *(uint4*)&Qs[lr*QSTR + lh2 + 4*j] =
                make_uint4(f2tf(v.x*0.125f), f2tf(v.y*0.125f),
                           f2tf(v.z*0.125f), f2tf(v.w*0.125f));
        }
    }

    float lacc[8];
    #pragma unroll
    for (int i = 0; i < 8; i++) lacc[i] = 0.f;
    float cacc[4][2][4];
    #pragma unroll
    for (int mi = 0; mi < 4; mi++)
        #pragma unroll
        for (int ni = 0; ni < 2; ni++)
            #pragma unroll
            for (int r = 0; r < 4; r++) cacc[mi][ni][r] = 0.f;

    for (int kt = 0; kt < 16; kt++) {
        __syncthreads();   // prev PV done with Vs / first-iter Qs+rowSum ready
        { // K,V tile loads (tf32 round)
            const float* kp = Kb + (size_t)(kt*128 + lr) * DK_ + lh2;
            const float* vp = Vb + (size_t)(kt*128 + lr) * DK_ + lh2;
            #pragma unroll
            for (int j = 0; j < 8; j++) {
                float4 kv = *(const float4*)(kp + 4*j);
                float4 vv = *(const float4*)(vp + 4*j);
                *(uint4*)&Ks[lr*QSTR + lh2 + 4*j] =
                    make_uint4(f2tf(kv.x), f2tf(kv.y), f2tf(kv.z), f2tf(kv.w));
                *(uint4*)&Vs[lr*QSTR + lh2 + 4*j] =
                    make_uint4(f2tf(vv.x), f2tf(vv.y), f2tf(vv.z), f2tf(vv.w));
            }
        }
        __syncthreads();

        // ---- scores: warp tile 64q x 32k, k-dim = 64 ----
        float sc[4][4][4];
        #pragma unroll
        for (int mi = 0; mi < 4; mi++)
            #pragma unroll
            for (int ni = 0; ni < 4; ni++)
                #pragma unroll
                for (int r = 0; r < 4; r++) sc[mi][ni][r] = 0.f;

        #pragma unroll
        for (int kc = 0; kc < 8; kc++) {
            unsigned a[4][4], bb[4][2];
            const int ab0 = (wm*64 + gr) * QSTR + kc*8 + tg;
            #pragma unroll
            for (int mi = 0; mi < 4; mi++) {
                a[mi][0] = Qs[ab0 + (mi*16    ) * QSTR];
                a[mi][1] = Qs[ab0 + (mi*16 + 8) * QSTR];
                a[mi][2] = Qs[ab0 + (mi*16    ) * QSTR + 4];
                a[mi][3] = Qs[ab0 + (mi*16 + 8) * QSTR + 4];
            }
            const int bb0 = (wn*32 + gr) * QSTR + kc*8 + tg;
            #pragma unroll
            for (int ni = 0; ni < 4; ni++) {
                bb[ni][0] = Ks[bb0 + ni*8 * QSTR];
                bb[ni][1] = Ks[bb0 + ni*8 * QSTR + 4];
            }
            #pragma unroll
            for (int mi = 0; mi < 4; mi++)
                #pragma unroll
                for (int ni = 0; ni < 4; ni++)
                    mma_tf32(sc[mi][ni], a[mi][0], a[mi][1], a[mi][2], a[mi][3],
                             bb[ni][0], bb[ni][1]);
        }

        // ---- mask + exp; write unnormalized probs to global + Ps(tf32) ----
        #pragma unroll
        for (int mi = 0; mi < 4; mi++) {
            const int r0 = wm*64 + mi*16 + gr;
            #pragma unroll
            for (int ni = 0; ni < 4; ni++) {
                const int ck = wn*32 + ni*8 + 2*tg;
                const size_t gcol = (size_t)kt*128 + ck;
                int2 mk0 = *(const int2*)&mb[(size_t)r0      * S_ + gcol];
                int2 mk1 = *(const int2*)&mb[(size_t)(r0+8)  * S_ + gcol];
                float p00 = mk0.x ? __expf(sc[mi][ni][0]) : 0.f;
                float p01 = mk0.y ? __expf(sc[mi][ni][1]) : 0.f;
                float p10 = mk1.x ? __expf(sc[mi][ni][2]) : 0.f;
                float p11 = mk1.y ? __expf(sc[mi][ni][3]) : 0.f;
                lacc[mi*2]   += p00 + p01;
                lacc[mi*2+1] += p10 + p11;
                *(float2*)&ab[(size_t)r0     * S_ + gcol] = make_float2(p00, p01);
                *(float2*)&ab[(size_t)(r0+8) * S_ + gcol] = make_float2(p10, p11);
                *(uint2*)&Ps[r0    *PSTR2 + ck] = make_uint2(f2tf(p00), f2tf(p01));
                *(uint2*)&Ps[(r0+8)*PSTR2 + ck] = make_uint2(f2tf(p10), f2tf(p11));
            }
        }
        __syncthreads();

        // ---- PV: warp tile 64q x 16d, k-dim = 128 keys ----
        #pragma unroll
        for (int kc = 0; kc < 16; kc++) {
            unsigned a[4][4], bb[2][2];
            const int ab0 = (wm*64 + gr) * PSTR2 + kc*8 + tg;
            #pragma unroll
            for (int mi = 0; mi < 4; mi++) {
                a[mi][0] = Ps[ab0 + (mi*16    ) * PSTR2];
                a[mi][1] = Ps[ab0 + (mi*16 + 8) * PSTR2];
                a[mi][2] = Ps[ab0 + (mi*16    ) * PSTR2 + 4];
                a[mi][3] = Ps[ab0 + (mi*16 + 8) * PSTR2 + 4];
            }
            const int vb0 = (kc*8 + tg) * QSTR + wn*16 + gr;
            #pragma unroll
            for (int ni = 0; ni < 2; ni++) {
                bb[ni][0] = Vs[vb0 + ni*8];
                bb[ni][1] = Vs[vb0 + 4*QSTR + ni*8];
            }
            #pragma unroll
            for (int mi = 0; mi < 4; mi++)
                #pragma unroll
                for (int ni = 0; ni < 2; ni++)
                    mma_tf32(cacc[mi][ni], a[mi][0], a[mi][1], a[mi][2], a[mi][3],
                             bb[ni][0], bb[ni][1]);
        }
    }

    // ---- row sums: quad shuffle reduce + cross-warp atomic ----
    #pragma unroll
    for (int i = 0; i < 8; i++) {
        float v = lacc[i];
        v += __shfl_xor_sync(0xffffffffu, v, 1);
        v += __shfl_xor_sync(0xffffffffu, v, 2);
        lacc[i] = v;
    }
    if (tg == 0) {
        #pragma unroll
        for (int mi = 0; mi < 4; mi++) {
            atomicAdd(&rowSum[wm*64 + mi*16 + gr],     lacc[mi*2]);
            atomicAdd(&rowSum[wm*64 + mi*16 + gr + 8], lacc[mi*2+1]);
        }
    }
    __syncthreads();
    if (tid < 128)
        g_invl[(size_t)bh * S_ + qt*128 + tid] = 1.0f / rowSum[tid];

    // ---- context write (scaled by 1/l), permuted to [b][s][h*64+d] ----
    #pragma unroll
    for (int mi = 0; mi < 4; mi++) {
        const int r0 = wm*64 + mi*16 + gr;
        const float s0 = 1.0f / rowSum[r0];
        const float s1 = 1.0f / rowSum[r0 + 8];
        #pragma unroll
        for (int ni = 0; ni < 2; ni++) {
            const int d = wn*16 + ni*8 + 2*tg;
            size_t d0 = ((size_t)(b*S_ + qt*128 + r0    )) * DM_ + h*DK_ + d;
            size_t d1 = ((size_t)(b*S_ + qt*128 + r0 + 8)) * DM_ + h*DK_ + d;
            *(float2*)&g_Ctx[d0] = make_float2(cacc[mi][ni][0]*s0, cacc[mi][ni][1]*s0);
            *(float2*)&g_Ctx[d1] = make_float2(cacc[mi][ni][2]*s1, cacc[mi][ni][3]*s1);
        }
    }
}

// ---------------------------------------------------------------------------
// Normalize attention rows: attn[row][:] *= invl[row]
// ---------------------------------------------------------------------------
__global__ __launch_bounds__(256) void rescale(float* __restrict__ attn)
{
    const int row = blockIdx.x;
    const float s = g_invl[row];
    float4* p = (float4*)(attn + (size_t)row * S_);
    const int t = threadIdx.x;
    float4 v0 = p[t], v1 = p[t + 256];
    v0.x *= s; v0.y *= s; v0.z *= s; v0.w *= s;
    v1.x *= s; v1.y *= s; v1.z *= s; v1.w *= s;
    p[t] = v0; p[t + 256] = v1;
}

// ---------------------------------------------------------------------------
extern "C" void kernel_launch(void* const* d_in, const int* in_sizes, int n_in,
                              void* d_out, int out_size)
{
    const float* q    = (const float*)d_in[0];
    const float* k    = (const float*)d_in[1];
    const float* v    = (const float*)d_in[2];
    const int*   mask = (const int*)  d_in[3];
    const float* Wq   = (const float*)d_in[4];
    const float* Wk   = (const float*)d_in[5];
    const float* Wv   = (const float*)d_in[6];
    const float* Wo   = (const float*)d_in[7];
    const float* bo   = (const float*)d_in[8];

    float* out      = (float*)d_out;
    float* ctx_out  = out;                             // [B,S,DM]
    float* attn_out = out + (size_t)B_ * S_ * DM_;     // [B,H,S,S]

    void *pQ, *pK, *pV, *pC;
    cudaGetSymbolAddress(&pQ, g_Qh);
    cudaGetSymbolAddress(&pK, g_Kh);
    cudaGetSymbolAddress(&pV, g_Vh);
    cudaGetSymbolAddress(&pC, g_Ctx);

    const int smemBytes = SM_WORDS * 4;   // 172544
    cudaFuncSetAttribute(attn_mma, cudaFuncAttributeMaxDynamicSharedMemorySize, smemBytes);

    dim3 gproj(M_/128, DM_/128);
    proj_mma<<<gproj, 256>>>(q, Wq, nullptr, (float*)pQ, 1);
    proj_mma<<<gproj, 256>>>(k, Wk, nullptr, (float*)pK, 1);
    proj_mma<<<gproj, 256>>>(v, Wv, nullptr, (float*)pV, 1);

    attn_mma<<<dim3(S_/128, B_*H_), 256, smemBytes>>>(mask, attn_out);

    rescale<<<B_*H_*S_, 256>>>(attn_out);

    proj_mma<<<gproj, 256>>>((const float*)pC, Wo, bo, ctx_out, 0);
}

// round 4
// speedup vs baseline: 2.6125x; 1.1343x over previous
#include <cuda_runtime.h>

#define B_  4
#define S_  2048
#define DM_ 1024
#define H_  16
#define DK_ 64
#define M_  (B_*S_)   // 8192 rows

// Scratch (allocation-free rule: __device__ globals)
__device__ float g_Qh[(size_t)B_*H_*S_*DK_];
__device__ float g_Kh[(size_t)B_*H_*S_*DK_];
__device__ float g_Vh[(size_t)B_*H_*S_*DK_];
__device__ float g_Ctx[(size_t)M_*DM_];
__device__ float g_invl[(size_t)B_*H_*S_];

// ---------------------------------------------------------------------------
// helpers
// ---------------------------------------------------------------------------
__device__ __forceinline__ unsigned f2tf(float x) {
    unsigned u;
    asm("cvt.rna.tf32.f32 %0, %1;" : "=r"(u) : "f"(x));
    return u;
}
__device__ __forceinline__ void mma_tf32(float c[4],
                                         unsigned a0, unsigned a1, unsigned a2, unsigned a3,
                                         unsigned b0, unsigned b1) {
    asm("mma.sync.aligned.m16n8k8.row.col.f32.tf32.tf32.f32 "
        "{%0,%1,%2,%3},{%4,%5,%6,%7},{%8,%9},{%0,%1,%2,%3};"
        : "+f"(c[0]), "+f"(c[1]), "+f"(c[2]), "+f"(c[3])
        : "r"(a0), "r"(a1), "r"(a2), "r"(a3), "r"(b0), "r"(b1));
}
__device__ __forceinline__ unsigned sm_u32(const void* p) {
    return (unsigned)__cvta_generic_to_shared(p);
}
__device__ __forceinline__ void ldsm4(unsigned r[4], unsigned addr) {
    asm volatile("ldmatrix.sync.aligned.m8n8.x4.shared.b16 {%0,%1,%2,%3}, [%4];"
        : "=r"(r[0]), "=r"(r[1]), "=r"(r[2]), "=r"(r[3]) : "r"(addr));
}

// ---------------------------------------------------------------------------
// Projection GEMM (tf32 mma + ldmatrix): Y = X @ W^T (+bias). 128x128 tile,
// BK=32, 8 warps 2(m)x4(n); warp = 64m x 32n.
// ---------------------------------------------------------------------------
#define XSTR 36
__global__ __launch_bounds__(256) void proj_mma(const float* __restrict__ X,
                                                const float* __restrict__ W,
                                                const float* __restrict__ bias,
                                                float* __restrict__ Y,
                                                int headsMode)
{
    __shared__ unsigned Xs[128 * XSTR];
    __shared__ unsigned Ws[128 * XSTR];
    const int tid = threadIdx.x;
    const int lane = tid & 31, wid = tid >> 5;
    const int wm = wid >> 2, wn = wid & 3;
    const int gr = lane >> 2, tg = lane & 3;
    const int m0 = blockIdx.x * 128, n0 = blockIdx.y * 128;

    const int arow = lane & 15;
    const int acol = ((lane >> 4) & 1) * 4;
    const int brow = ((lane >> 4) & 1) * 8 + (lane & 7);
    const int bcol = ((lane >> 3) & 1) * 4;
    const unsigned abase = sm_u32(Xs + (wm*64 + arow)*XSTR + acol);
    const unsigned bbase = sm_u32(Ws + (wn*32 + brow)*XSTR + bcol);

    const int lr = tid >> 1;          // 0..127 (row)
    const int lh = (tid & 1) * 16;    // k-half

    float c[4][4][4];
    #pragma unroll
    for (int mi = 0; mi < 4; mi++)
        #pragma unroll
        for (int ni = 0; ni < 4; ni++)
            #pragma unroll
            for (int r = 0; r < 4; r++) c[mi][ni][r] = 0.f;

    float4 px[4], pw[4];
    {
        const float* Xp = X + (size_t)(m0 + lr) * DM_ + lh;
        const float* Wp = W + (size_t)(n0 + lr) * DM_ + lh;
        #pragma unroll
        for (int j = 0; j < 4; j++) { px[j] = *(const float4*)(Xp + 4*j); pw[j] = *(const float4*)(Wp + 4*j); }
    }

    for (int kt = 0; kt < DM_; kt += 32) {
        #pragma unroll
        for (int j = 0; j < 4; j++) {
            uint4 ux = make_uint4(f2tf(px[j].x), f2tf(px[j].y), f2tf(px[j].z), f2tf(px[j].w));
            uint4 uw = make_uint4(f2tf(pw[j].x), f2tf(pw[j].y), f2tf(pw[j].z), f2tf(pw[j].w));
            *(uint4*)&Xs[lr * XSTR + lh + 4*j] = ux;
            *(uint4*)&Ws[lr * XSTR + lh + 4*j] = uw;
        }
        __syncthreads();

        if (kt + 32 < DM_) {
            const float* Xp = X + (size_t)(m0 + lr) * DM_ + kt + 32 + lh;
            const float* Wp = W + (size_t)(n0 + lr) * DM_ + kt + 32 + lh;
            #pragma unroll
            for (int j = 0; j < 4; j++) { px[j] = *(const float4*)(Xp + 4*j); pw[j] = *(const float4*)(Wp + 4*j); }
        }

        #pragma unroll
        for (int kc = 0; kc < 4; kc++) {
            unsigned a[4][4], bb[4][2];
            #pragma unroll
            for (int mi = 0; mi < 4; mi++)
                ldsm4(a[mi], abase + (unsigned)(mi*16*XSTR + kc*8) * 4u);
            #pragma unroll
            for (int np = 0; np < 2; np++) {
                unsigned t[4];
                ldsm4(t, bbase + (unsigned)(np*16*XSTR + kc*8) * 4u);
                bb[2*np][0] = t[0]; bb[2*np][1] = t[1];
                bb[2*np+1][0] = t[2]; bb[2*np+1][1] = t[3];
            }
            #pragma unroll
            for (int mi = 0; mi < 4; mi++)
                #pragma unroll
                for (int ni = 0; ni < 4; ni++)
                    mma_tf32(c[mi][ni], a[mi][0], a[mi][1], a[mi][2], a[mi][3],
                             bb[ni][0], bb[ni][1]);
        }
        __syncthreads();
    }

    if (headsMode) {
        #pragma unroll
        for (int mi = 0; mi < 4; mi++) {
            int m = m0 + wm*64 + mi*16 + gr;
            int b = m >> 11, s = m & (S_ - 1);
            #pragma unroll
            for (int ni = 0; ni < 4; ni++) {
                int n = n0 + wn*32 + ni*8 + 2*tg;
                int h = n >> 6, dk = n & 63;
                size_t base = (((size_t)(b*H_ + h) * S_) + s) * DK_ + dk;
                *(float2*)&Y[base]         = make_float2(c[mi][ni][0], c[mi][ni][1]);
                *(float2*)&Y[base + 8*DK_] = make_float2(c[mi][ni][2], c[mi][ni][3]);
            }
        }
    } else {
        #pragma unroll
        for (int mi = 0; mi < 4; mi++) {
            int m = m0 + wm*64 + mi*16 + gr;
            #pragma unroll
            for (int ni = 0; ni < 4; ni++) {
                int n = n0 + wn*32 + ni*8 + 2*tg;
                float b0 = bias[n], b1 = bias[n+1];
                *(float2*)&Y[(size_t)m * DM_ + n] =
                    make_float2(c[mi][ni][0] + b0, c[mi][ni][1] + b1);
                *(float2*)&Y[(size_t)(m+8) * DM_ + n] =
                    make_float2(c[mi][ni][2] + b0, c[mi][ni][3] + b1);
            }
        }
    }
}

// ---------------------------------------------------------------------------
// Fused attention (tf32 mma + ldmatrix). CTA: 128 queries, 16 key-tiles of 128.
// Scores: 8 warps as 2(m)x4(n), warp 64q x 32k. PV: 8 warps as 4(m)x2(n),
// warp 32q x 32d, k=128 keys. V stored transposed (Vt[d][key]) for LDSM B.
// smem words: Qs 128*68 | Ks 128*68 | Vt 64*132 | Ps 128*132 | rowSum 128
// ---------------------------------------------------------------------------
#define QSTR 68
#define VTSTR 132
#define PSTR2 132
#define OFF_KS 8704
#define OFF_VT 17408
#define OFF_PS 25856
#define OFF_RS 42752
#define SM_WORDS 42880

__global__ __launch_bounds__(256) void attn_mma(const int* __restrict__ mask,
                                                float* __restrict__ attn)
{
    extern __shared__ unsigned smu[];
    unsigned* Qs = smu;
    unsigned* Ks = smu + OFF_KS;
    unsigned* Vt = smu + OFF_VT;
    unsigned* Ps = smu + OFF_PS;
    float* rowSum = (float*)(smu + OFF_RS);

    const int tid = threadIdx.x;
    const int lane = tid & 31, wid = tid >> 5;
    const int wm = wid >> 2, wn = wid & 3;       // score mapping
    const int wm2 = wid & 3, wn2 = wid >> 2;     // PV mapping
    const int gr = lane >> 2, tg = lane & 3;
    const int qt = blockIdx.x, bh = blockIdx.y;
    const int b = bh >> 4, h = bh & 15;

    const int arow = lane & 15;
    const int acol = ((lane >> 4) & 1) * 4;
    const int brow = ((lane >> 4) & 1) * 8 + (lane & 7);
    const int bcol = ((lane >> 3) & 1) * 4;
    const unsigned qbase = sm_u32(Qs + (wm*64 + arow)*QSTR + acol);
    const unsigned kbase = sm_u32(Ks + (wn*32 + brow)*QSTR + bcol);
    const unsigned pbase = sm_u32(Ps + (wm2*32 + arow)*PSTR2 + acol);
    const unsigned vbase = sm_u32(Vt + (wn2*32 + brow)*VTSTR + bcol);

    const float* Qb = g_Qh + ((size_t)bh * S_ + qt*128) * DK_;
    const float* Kb = g_Kh + (size_t)bh * S_ * DK_;
    const float* Vb = g_Vh + (size_t)bh * S_ * DK_;
    const int*   mb = mask + (size_t)b * S_ * S_ + (size_t)qt * 128 * S_;
    float*       ab = attn + (size_t)bh * S_ * S_ + (size_t)qt * 128 * S_;

    if (tid < 128) rowSum[tid] = 0.f;

    const int lr = tid >> 1;            // 0..127
    const int lh2 = (tid & 1) * 32;     // d-half
    { // Q load: scale by 1/sqrt(64), tf32 round
        const float* qp = Qb + (size_t)lr * DK_ + lh2;
        #pragma unroll
        for (int j = 0; j < 8; j++) {
            float4 v = *(const float4*)(qp + 4*j);
            *(uint4*)&Qs[lr*QSTR + lh2 + 4*j] =
                make_uint4(f2tf(v.x*0.125f), f2tf(v.y*0.125f),
                           f2tf(v.z*0.125f), f2tf(v.w*0.125f));
        }
    }

    float lacc[8];
    #pragma unroll
    for (int i = 0; i < 8; i++) lacc[i] = 0.f;
    float cacc[2][4][4];
    #pragma unroll
    for (int mi = 0; mi < 2; mi++)
        #pragma unroll
        for (int ni = 0; ni < 4; ni++)
            #pragma unroll
            for (int r = 0; r < 4; r++) cacc[mi][ni][r] = 0.f;

    for (int kt = 0; kt < 16; kt++) {
        __syncthreads();   // prev PV done with Vt/Ps; first iter: Qs/rowSum ready
        { // K row-major, V transposed (tf32 round)
            const float* kp = Kb + (size_t)(kt*128 + lr) * DK_ + lh2;
            const float* vp = Vb + (size_t)(kt*128 + lr) * DK_ + lh2;
            #pragma unroll
            for (int j = 0; j < 8; j++) {
                float4 kv = *(const float4*)(kp + 4*j);
                *(uint4*)&Ks[lr*QSTR + lh2 + 4*j] =
                    make_uint4(f2tf(kv.x), f2tf(kv.y), f2tf(kv.z), f2tf(kv.w));
                float4 vv = *(const float4*)(vp + 4*j);
                int d = lh2 + 4*j;
                Vt[(d+0)*VTSTR + lr] = f2tf(vv.x);
                Vt[(d+1)*VTSTR + lr] = f2tf(vv.y);
                Vt[(d+2)*VTSTR + lr] = f2tf(vv.z);
                Vt[(d+3)*VTSTR + lr] = f2tf(vv.w);
            }
        }
        // mask prefetch (hidden under sync + score mma)
        int2 mk0[4][4], mk1[4][4];
        #pragma unroll
        for (int mi = 0; mi < 4; mi++) {
            const int r0 = wm*64 + mi*16 + gr;
            #pragma unroll
            for (int ni = 0; ni < 4; ni++) {
                const size_t gcol = (size_t)kt*128 + wn*32 + ni*8 + 2*tg;
                mk0[mi][ni] = *(const int2*)&mb[(size_t)r0     * S_ + gcol];
                mk1[mi][ni] = *(const int2*)&mb[(size_t)(r0+8) * S_ + gcol];
            }
        }
        __syncthreads();

        // ---- scores: warp tile 64q x 32k, k-dim = 64 ----
        float sc[4][4][4];
        #pragma unroll
        for (int mi = 0; mi < 4; mi++)
            #pragma unroll
            for (int ni = 0; ni < 4; ni++)
                #pragma unroll
                for (int r = 0; r < 4; r++) sc[mi][ni][r] = 0.f;

        #pragma unroll
        for (int kc = 0; kc < 8; kc++) {
            unsigned a[4][4], bb[4][2];
            #pragma unroll
            for (int mi = 0; mi < 4; mi++)
                ldsm4(a[mi], qbase + (unsigned)(mi*16*QSTR + kc*8) * 4u);
            #pragma unroll
            for (int np = 0; np < 2; np++) {
                unsigned t[4];
                ldsm4(t, kbase + (unsigned)(np*16*QSTR + kc*8) * 4u);
                bb[2*np][0] = t[0]; bb[2*np][1] = t[1];
                bb[2*np+1][0] = t[2]; bb[2*np+1][1] = t[3];
            }
            #pragma unroll
            for (int mi = 0; mi < 4; mi++)
                #pragma unroll
                for (int ni = 0; ni < 4; ni++)
                    mma_tf32(sc[mi][ni], a[mi][0], a[mi][1], a[mi][2], a[mi][3],
                             bb[ni][0], bb[ni][1]);
        }

        // ---- mask + exp; unnormalized probs -> global + Ps(tf32) ----
        #pragma unroll
        for (int mi = 0; mi < 4; mi++) {
            const int r0 = wm*64 + mi*16 + gr;
            #pragma unroll
            for (int ni = 0; ni < 4; ni++) {
                const int ck = wn*32 + ni*8 + 2*tg;
                const size_t gcol = (size_t)kt*128 + ck;
                float p00 = mk0[mi][ni].x ? __expf(sc[mi][ni][0]) : 0.f;
                float p01 = mk0[mi][ni].y ? __expf(sc[mi][ni][1]) : 0.f;
                float p10 = mk1[mi][ni].x ? __expf(sc[mi][ni][2]) : 0.f;
                float p11 = mk1[mi][ni].y ? __expf(sc[mi][ni][3]) : 0.f;
                lacc[mi*2]   += p00 + p01;
                lacc[mi*2+1] += p10 + p11;
                *(float2*)&ab[(size_t)r0     * S_ + gcol] = make_float2(p00, p01);
                *(float2*)&ab[(size_t)(r0+8) * S_ + gcol] = make_float2(p10, p11);
                *(uint2*)&Ps[r0    *PSTR2 + ck] = make_uint2(f2tf(p00), f2tf(p01));
                *(uint2*)&Ps[(r0+8)*PSTR2 + ck] = make_uint2(f2tf(p10), f2tf(p11));
            }
        }
        __syncthreads();

        // ---- PV: warp tile 32q x 32d, k-dim = 128 keys ----
        #pragma unroll
        for (int kc = 0; kc < 16; kc++) {
            unsigned a2[2][4], vb[4][2];
            ldsm4(a2[0], pbase + (unsigned)(kc*8) * 4u);
            ldsm4(a2[1], pbase + (unsigned)(16*PSTR2 + kc*8) * 4u);
            #pragma unroll
            for (int np = 0; np < 2; np++) {
                unsigned t[4];
                ldsm4(t, vbase + (unsigned)(np*16*VTSTR + kc*8) * 4u);
                vb[2*np][0] = t[0]; vb[2*np][1] = t[1];
                vb[2*np+1][0] = t[2]; vb[2*np+1][1] = t[3];
            }
            #pragma unroll
            for (int mi = 0; mi < 2; mi++)
                #pragma unroll
                for (int ni = 0; ni < 4; ni++)
                    mma_tf32(cacc[mi][ni], a2[mi][0], a2[mi][1], a2[mi][2], a2[mi][3],
                             vb[ni][0], vb[ni][1]);
        }
    }

    // ---- row sums: quad shuffle reduce + cross-warp atomic ----
    #pragma unroll
    for (int i = 0; i < 8; i++) {
        float v = lacc[i];
        v += __shfl_xor_sync(0xffffffffu, v, 1);
        v += __shfl_xor_sync(0xffffffffu, v, 2);
        lacc[i] = v;
    }
    if (tg == 0) {
        #pragma unroll
        for (int mi = 0; mi < 4; mi++) {
            atomicAdd(&rowSum[wm*64 + mi*16 + gr],     lacc[mi*2]);
            atomicAdd(&rowSum[wm*64 + mi*16 + gr + 8], lacc[mi*2+1]);
        }
    }
    __syncthreads();
    if (tid < 128)
        g_invl[(size_t)bh * S_ + qt*128 + tid] = 1.0f / rowSum[tid];

    // ---- context write (scaled by 1/l), permuted to [b][s][h*64+d] ----
    #pragma unroll
    for (int mi = 0; mi < 2; mi++) {
        const int r0 = wm2*32 + mi*16 + gr;
        const float s0 = 1.0f / rowSum[r0];
        const float s1 = 1.0f / rowSum[r0 + 8];
        #pragma unroll
        for (int ni = 0; ni < 4; ni++) {
            const int d = wn2*32 + ni*8 + 2*tg;
            size_t d0 = ((size_t)(b*S_ + qt*128 + r0    )) * DM_ + h*DK_ + d;
            size_t d1 = ((size_t)(b*S_ + qt*128 + r0 + 8)) * DM_ + h*DK_ + d;
            *(float2*)&g_Ctx[d0] = make_float2(cacc[mi][ni][0]*s0, cacc[mi][ni][1]*s0);
            *(float2*)&g_Ctx[d1] = make_float2(cacc[mi][ni][2]*s1, cacc[mi][ni][3]*s1);
        }
    }
}

// ---------------------------------------------------------------------------
// Normalize attention rows: attn[row][:] *= invl[row]
// ---------------------------------------------------------------------------
__global__ __launch_bounds__(256) void rescale(float* __restrict__ attn)
{
    const int row = blockIdx.x;
    const float s = g_invl[row];
    float4* p = (float4*)(attn + (size_t)row * S_);
    const int t = threadIdx.x;
    float4 v0 = p[t], v1 = p[t + 256];
    v0.x *= s; v0.y *= s; v0.z *= s; v0.w *= s;
    v1.x *= s; v1.y *= s; v1.z *= s; v1.w *= s;
    p[t] = v0; p[t + 256] = v1;
}

// ---------------------------------------------------------------------------
extern "C" void kernel_launch(void* const* d_in, const int* in_sizes, int n_in,
                              void* d_out, int out_size)
{
    const float* q    = (const float*)d_in[0];
    const float* k    = (const float*)d_in[1];
    const float* v    = (const float*)d_in[2];
    const int*   mask = (const int*)  d_in[3];
    const float* Wq   = (const float*)d_in[4];
    const float* Wk   = (const float*)d_in[5];
    const float* Wv   = (const float*)d_in[6];
    const float* Wo   = (const float*)d_in[7];
    const float* bo   = (const float*)d_in[8];

    float* out      = (float*)d_out;
    float* ctx_out  = out;                             // [B,S,DM]
    float* attn_out = out + (size_t)B_ * S_ * DM_;     // [B,H,S,S]

    void *pQ, *pK, *pV, *pC;
    cudaGetSymbolAddress(&pQ, g_Qh);
    cudaGetSymbolAddress(&pK, g_Kh);
    cudaGetSymbolAddress(&pV, g_Vh);
    cudaGetSymbolAddress(&pC, g_Ctx);

    const int smemBytes = SM_WORDS * 4;   // 171520
    cudaFuncSetAttribute(attn_mma, cudaFuncAttributeMaxDynamicSharedMemorySize, smemBytes);

    dim3 gproj(M_/128, DM_/128);
    proj_mma<<<gproj, 256>>>(q, Wq, nullptr, (float*)pQ, 1);
    proj_mma<<<gproj, 256>>>(k, Wk, nullptr, (float*)pK, 1);
    proj_mma<<<gproj, 256>>>(v, Wv, nullptr, (float*)pV, 1);

    attn_mma<<<dim3(S_/128, B_*H_), 256, smemBytes>>>(mask, attn_out);

    rescale<<<B_*H_*S_, 256>>>(attn_out);

    proj_mma<<<gproj, 256>>>((const float*)pC, Wo, bo, ctx_out, 0);
}

// round 5
// speedup vs baseline: 2.8240x; 1.0809x over previous
#include <cuda_runtime.h>

#define B_  4
#define S_  2048
#define DM_ 1024
#define H_  16
#define DK_ 64
#define M_  (B_*S_)   // 8192 rows

// Scratch (allocation-free rule: __device__ globals)
__device__ float g_Qh[(size_t)B_*H_*S_*DK_];
__device__ float g_Kh[(size_t)B_*H_*S_*DK_];
__device__ float g_Vh[(size_t)B_*H_*S_*DK_];
__device__ float g_Ctx[(size_t)M_*DM_];
__device__ float g_invl[(size_t)B_*H_*S_];
__device__ unsigned g_mbits[(size_t)B_*S_*(S_/32)];   // packed mask bits

// ---------------------------------------------------------------------------
// helpers
// ---------------------------------------------------------------------------
__device__ __forceinline__ unsigned f2tf(float x) {
    unsigned u;
    asm("cvt.rna.tf32.f32 %0, %1;" : "=r"(u) : "f"(x));
    return u;
}
__device__ __forceinline__ void mma_tf32(float c[4],
                                         unsigned a0, unsigned a1, unsigned a2, unsigned a3,
                                         unsigned b0, unsigned b1) {
    asm("mma.sync.aligned.m16n8k8.row.col.f32.tf32.tf32.f32 "
        "{%0,%1,%2,%3},{%4,%5,%6,%7},{%8,%9},{%0,%1,%2,%3};"
        : "+f"(c[0]), "+f"(c[1]), "+f"(c[2]), "+f"(c[3])
        : "r"(a0), "r"(a1), "r"(a2), "r"(a3), "r"(b0), "r"(b1));
}
__device__ __forceinline__ unsigned sm_u32(const void* p) {
    return (unsigned)__cvta_generic_to_shared(p);
}
__device__ __forceinline__ void ldsm4(unsigned r[4], unsigned addr) {
    asm volatile("ldmatrix.sync.aligned.m8n8.x4.shared.b16 {%0,%1,%2,%3}, [%4];"
        : "=r"(r[0]), "=r"(r[1]), "=r"(r[2]), "=r"(r[3]) : "r"(addr));
}

// ---------------------------------------------------------------------------
// Pack mask into bits: g_mbits[b][row][w] bit j = (mask[b][row][32w+j] != 0)
// ---------------------------------------------------------------------------
__global__ __launch_bounds__(256) void pack_mask(const int* __restrict__ mask)
{
    const int lane = threadIdx.x & 31;
    const int gw = blockIdx.x * 8 + (threadIdx.x >> 5);   // global word index
    int m = mask[(size_t)gw * 32 + lane];
    unsigned bits = __ballot_sync(0xffffffffu, m != 0);
    if (lane == 0) g_mbits[gw] = bits;
}

// ---------------------------------------------------------------------------
// Projection GEMM (tf32 mma + ldmatrix): Y = X @ W^T (+bias). 128x128 tile,
// BK=32, 8 warps 2(m)x4(n); warp = 64m x 32n.   (unchanged from R4)
// ---------------------------------------------------------------------------
#define XSTR 36
__global__ __launch_bounds__(256) void proj_mma(const float* __restrict__ X,
                                                const float* __restrict__ W,
                                                const float* __restrict__ bias,
                                                float* __restrict__ Y,
                                                int headsMode)
{
    __shared__ unsigned Xs[128 * XSTR];
    __shared__ unsigned Ws[128 * XSTR];
    const int tid = threadIdx.x;
    const int lane = tid & 31, wid = tid >> 5;
    const int wm = wid >> 2, wn = wid & 3;
    const int gr = lane >> 2, tg = lane & 3;
    const int m0 = blockIdx.x * 128, n0 = blockIdx.y * 128;

    const int arow = lane & 15;
    const int acol = ((lane >> 4) & 1) * 4;
    const int brow = ((lane >> 4) & 1) * 8 + (lane & 7);
    const int bcol = ((lane >> 3) & 1) * 4;
    const unsigned abase = sm_u32(Xs + (wm*64 + arow)*XSTR + acol);
    const unsigned bbase = sm_u32(Ws + (wn*32 + brow)*XSTR + bcol);

    const int lr = tid >> 1;          // 0..127 (row)
    const int lh = (tid & 1) * 16;    // k-half

    float c[4][4][4];
    #pragma unroll
    for (int mi = 0; mi < 4; mi++)
        #pragma unroll
        for (int ni = 0; ni < 4; ni++)
            #pragma unroll
            for (int r = 0; r < 4; r++) c[mi][ni][r] = 0.f;

    float4 px[4], pw[4];
    {
        const float* Xp = X + (size_t)(m0 + lr) * DM_ + lh;
        const float* Wp = W + (size_t)(n0 + lr) * DM_ + lh;
        #pragma unroll
        for (int j = 0; j < 4; j++) { px[j] = *(const float4*)(Xp + 4*j); pw[j] = *(const float4*)(Wp + 4*j); }
    }

    for (int kt = 0; kt < DM_; kt += 32) {
        #pragma unroll
        for (int j = 0; j < 4; j++) {
            uint4 ux = make_uint4(f2tf(px[j].x), f2tf(px[j].y), f2tf(px[j].z), f2tf(px[j].w));
            uint4 uw = make_uint4(f2tf(pw[j].x), f2tf(pw[j].y), f2tf(pw[j].z), f2tf(pw[j].w));
            *(uint4*)&Xs[lr * XSTR + lh + 4*j] = ux;
            *(uint4*)&Ws[lr * XSTR + lh + 4*j] = uw;
        }
        __syncthreads();

        if (kt + 32 < DM_) {
            const float* Xp = X + (size_t)(m0 + lr) * DM_ + kt + 32 + lh;
            const float* Wp = W + (size_t)(n0 + lr) * DM_ + kt + 32 + lh;
            #pragma unroll
            for (int j = 0; j < 4; j++) { px[j] = *(const float4*)(Xp + 4*j); pw[j] = *(const float4*)(Wp + 4*j); }
        }

        #pragma unroll
        for (int kc = 0; kc < 4; kc++) {
            unsigned a[4][4], bb[4][2];
            #pragma unroll
            for (int mi = 0; mi < 4; mi++)
                ldsm4(a[mi], abase + (unsigned)(mi*16*XSTR + kc*8) * 4u);
            #pragma unroll
            for (int np = 0; np < 2; np++) {
                unsigned t[4];
                ldsm4(t, bbase + (unsigned)(np*16*XSTR + kc*8) * 4u);
                bb[2*np][0] = t[0]; bb[2*np][1] = t[1];
                bb[2*np+1][0] = t[2]; bb[2*np+1][1] = t[3];
            }
            #pragma unroll
            for (int mi = 0; mi < 4; mi++)
                #pragma unroll
                for (int ni = 0; ni < 4; ni++)
                    mma_tf32(c[mi][ni], a[mi][0], a[mi][1], a[mi][2], a[mi][3],
                             bb[ni][0], bb[ni][1]);
        }
        __syncthreads();
    }

    if (headsMode) {
        #pragma unroll
        for (int mi = 0; mi < 4; mi++) {
            int m = m0 + wm*64 + mi*16 + gr;
            int b = m >> 11, s = m & (S_ - 1);
            #pragma unroll
            for (int ni = 0; ni < 4; ni++) {
                int n = n0 + wn*32 + ni*8 + 2*tg;
                int h = n >> 6, dk = n & 63;
                size_t base = (((size_t)(b*H_ + h) * S_) + s) * DK_ + dk;
                *(float2*)&Y[base]         = make_float2(c[mi][ni][0], c[mi][ni][1]);
                *(float2*)&Y[base + 8*DK_] = make_float2(c[mi][ni][2], c[mi][ni][3]);
            }
        }
    } else {
        #pragma unroll
        for (int mi = 0; mi < 4; mi++) {
            int m = m0 + wm*64 + mi*16 + gr;
            #pragma unroll
            for (int ni = 0; ni < 4; ni++) {
                int n = n0 + wn*32 + ni*8 + 2*tg;
                float b0 = bias[n], b1 = bias[n+1];
                *(float2*)&Y[(size_t)m * DM_ + n] =
                    make_float2(c[mi][ni][0] + b0, c[mi][ni][1] + b1);
                *(float2*)&Y[(size_t)(m+8) * DM_ + n] =
                    make_float2(c[mi][ni][2] + b0, c[mi][ni][3] + b1);
            }
        }
    }
}

// ---------------------------------------------------------------------------
// Fused attention, 512 threads / 16 warps. CTA: 128 queries, 16 key-tiles.
// Scores: warps 4(m)x4(n), warp 32q x 32k, ldmatrix A/B. PV: warps 4(m)x4(n),
// warp 32q x 16d, A (P) via ldmatrix, B (V natural, stride 72) via scalar LDS.
// Mask from packed bits (4 LDG.32 / thread / tile).
// smem words: Qs 128*68 | Ks 128*68 | Vs 128*72 | Ps 128*132 | rowSum 128
// ---------------------------------------------------------------------------
#define QSTR 68
#define VSTR 72
#define PSTR2 132
#define OFF_KS 8704
#define OFF_VS 17408
#define OFF_PS 26624
#define OFF_RS 43520
#define SM_WORDS 43648

__global__ __launch_bounds__(512) void attn_mma(float* __restrict__ attn)
{
    extern __shared__ unsigned smu[];
    unsigned* Qs = smu;
    unsigned* Ks = smu + OFF_KS;
    unsigned* Vs = smu + OFF_VS;   // natural [key][d], stride 72
    unsigned* Ps = smu + OFF_PS;
    float* rowSum = (float*)(smu + OFF_RS);

    const int tid = threadIdx.x;
    const int lane = tid & 31, wid = tid >> 5;
    const int wm = wid >> 2, wn = wid & 3;       // score map: 32q x 32k
    const int wm2 = wid & 3, wn2 = wid >> 2;     // PV map:    32q x 16d
    const int gr = lane >> 2, tg = lane & 3;
    const int qt = blockIdx.x, bh = blockIdx.y;
    const int b = bh >> 4, h = bh & 15;

    const int arow = lane & 15;
    const int acol = ((lane >> 4) & 1) * 4;
    const int brow = ((lane >> 4) & 1) * 8 + (lane & 7);
    const int bcol = ((lane >> 3) & 1) * 4;
    const unsigned qbase = sm_u32(Qs + (wm*32 + arow)*QSTR + acol);
    const unsigned kbase = sm_u32(Ks + (wn*32 + brow)*QSTR + bcol);
    const unsigned pbase = sm_u32(Ps + (wm2*32 + arow)*PSTR2 + acol);

    const float* Qb = g_Qh + ((size_t)bh * S_ + qt*128) * DK_;
    const float* Kb = g_Kh + (size_t)bh * S_ * DK_;
    const float* Vb = g_Vh + (size_t)bh * S_ * DK_;
    const unsigned* mbp = g_mbits + ((size_t)b * S_ + qt*128) * (S_/32);
    float* ab = attn + (size_t)bh * S_ * S_ + (size_t)qt * 128 * S_;

    if (tid < 128) rowSum[tid] = 0.f;

    const int lr = tid >> 2;            // 0..127
    const int seg = (tid & 3) * 16;     // d quarter
    { // Q load: scale by 1/sqrt(64), tf32 round
        const float* qp = Qb + (size_t)lr * DK_ + seg;
        #pragma unroll
        for (int j = 0; j < 4; j++) {
            float4 v = *(const float4*)(qp + 4*j);
            *(uint4*)&Qs[lr*QSTR + seg + 4*j] =
                make_uint4(f2tf(v.x*0.125f), f2tf(v.y*0.125f),
                           f2tf(v.z*0.125f), f2tf(v.w*0.125f));
        }
    }

    float lacc[4];
    #pragma unroll
    for (int i = 0; i < 4; i++) lacc[i] = 0.f;
    float cacc[2][2][4];
    #pragma unroll
    for (int mi = 0; mi < 2; mi++)
        #pragma unroll
        for (int f = 0; f < 2; f++)
            #pragma unroll
            for (int r = 0; r < 4; r++) cacc[mi][f][r] = 0.f;

    for (int kt = 0; kt < 16; kt++) {
        __syncthreads();   // prev PV done with Vs/Ps; first iter: Qs/rowSum ready
        // mask word prefetch (bits for this warp's 32-key window)
        unsigned mw[2][2];
        #pragma unroll
        for (int mi = 0; mi < 2; mi++) {
            const int r0 = wm*32 + mi*16 + gr;
            mw[mi][0] = mbp[(size_t)r0      * (S_/32) + kt*4 + wn];
            mw[mi][1] = mbp[(size_t)(r0+8)  * (S_/32) + kt*4 + wn];
        }
        { // K (row-major, stride 68) and V (natural, stride 72), tf32 round
            const float* kp = Kb + (size_t)(kt*128 + lr) * DK_ + seg;
            const float* vp = Vb + (size_t)(kt*128 + lr) * DK_ + seg;
            #pragma unroll
            for (int j = 0; j < 4; j++) {
                float4 kv = *(const float4*)(kp + 4*j);
                *(uint4*)&Ks[lr*QSTR + seg + 4*j] =
                    make_uint4(f2tf(kv.x), f2tf(kv.y), f2tf(kv.z), f2tf(kv.w));
                float4 vv = *(const float4*)(vp + 4*j);
                *(uint4*)&Vs[lr*VSTR + seg + 4*j] =
                    make_uint4(f2tf(vv.x), f2tf(vv.y), f2tf(vv.z), f2tf(vv.w));
            }
        }
        __syncthreads();

        // ---- scores: warp tile 32q x 32k, k-dim = 64 ----
        float sc[2][4][4];
        #pragma unroll
        for (int mi = 0; mi < 2; mi++)
            #pragma unroll
            for (int ni = 0; ni < 4; ni++)
                #pragma unroll
                for (int r = 0; r < 4; r++) sc[mi][ni][r] = 0.f;

        #pragma unroll
        for (int kc = 0; kc < 8; kc++) {
            unsigned a[2][4], bb[4][2];
            #pragma unroll
            for (int mi = 0; mi < 2; mi++)
                ldsm4(a[mi], qbase + (unsigned)(mi*16*QSTR + kc*8) * 4u);
            #pragma unroll
            for (int np = 0; np < 2; np++) {
                unsigned t[4];
                ldsm4(t, kbase + (unsigned)(np*16*QSTR + kc*8) * 4u);
                bb[2*np][0] = t[0]; bb[2*np][1] = t[1];
                bb[2*np+1][0] = t[2]; bb[2*np+1][1] = t[3];
            }
            #pragma unroll
            for (int mi = 0; mi < 2; mi++)
                #pragma unroll
                for (int ni = 0; ni < 4; ni++)
                    mma_tf32(sc[mi][ni], a[mi][0], a[mi][1], a[mi][2], a[mi][3],
                             bb[ni][0], bb[ni][1]);
        }

        // ---- mask(bits) + exp; unnormalized probs -> global(fp32) + Ps(tf32) ----
        #pragma unroll
        for (int mi = 0; mi < 2; mi++) {
            const int r0 = wm*32 + mi*16 + gr;
            #pragma unroll
            for (int ni = 0; ni < 4; ni++) {
                const int ck = wn*32 + ni*8 + 2*tg;
                const int bit = ni*8 + 2*tg;
                const size_t gcol = (size_t)kt*128 + ck;
                float p00 = (mw[mi][0] >> bit     & 1u) ? __expf(sc[mi][ni][0]) : 0.f;
                float p01 = (mw[mi][0] >> (bit+1) & 1u) ? __expf(sc[mi][ni][1]) : 0.f;
                float p10 = (mw[mi][1] >> bit     & 1u) ? __expf(sc[mi][ni][2]) : 0.f;
                float p11 = (mw[mi][1] >> (bit+1) & 1u) ? __expf(sc[mi][ni][3]) : 0.f;
                lacc[mi*2]   += p00 + p01;
                lacc[mi*2+1] += p10 + p11;
                *(float2*)&ab[(size_t)r0     * S_ + gcol] = make_float2(p00, p01);
                *(float2*)&ab[(size_t)(r0+8) * S_ + gcol] = make_float2(p10, p11);
                *(uint2*)&Ps[r0    *PSTR2 + ck] = make_uint2(f2tf(p00), f2tf(p01));
                *(uint2*)&Ps[(r0+8)*PSTR2 + ck] = make_uint2(f2tf(p10), f2tf(p11));
            }
        }
        __syncthreads();

        // ---- PV: warp tile 32q x 16d, k-dim = 128 keys ----
        // B frags via scalar LDS (conflict-free: bank = 8*tg + gr + const)
        #pragma unroll
        for (int kc = 0; kc < 16; kc++) {
            unsigned a2[2][4];
            ldsm4(a2[0], pbase + (unsigned)(kc*8) * 4u);
            ldsm4(a2[1], pbase + (unsigned)(16*PSTR2 + kc*8) * 4u);
            unsigned vb[2][2];
            #pragma unroll
            for (int f = 0; f < 2; f++) {
                const int d = wn2*16 + f*8 + gr;
                vb[f][0] = Vs[(kc*8 + tg    )*VSTR + d];
                vb[f][1] = Vs[(kc*8 + tg + 4)*VSTR + d];
            }
            #pragma unroll
            for (int mi = 0; mi < 2; mi++)
                #pragma unroll
                for (int f = 0; f < 2; f++)
                    mma_tf32(cacc[mi][f], a2[mi][0], a2[mi][1], a2[mi][2], a2[mi][3],
                             vb[f][0], vb[f][1]);
        }
    }

    // ---- row sums: quad shuffle reduce + cross-warp atomic ----
    #pragma unroll
    for (int i = 0; i < 4; i++) {
        float v = lacc[i];
        v += __shfl_xor_sync(0xffffffffu, v, 1);
        v += __shfl_xor_sync(0xffffffffu, v, 2);
        lacc[i] = v;
    }
    if (tg == 0) {
        #pragma unroll
        for (int mi = 0; mi < 2; mi++) {
            atomicAdd(&rowSum[wm*32 + mi*16 + gr],     lacc[mi*2]);
            atomicAdd(&rowSum[wm*32 + mi*16 + gr + 8], lacc[mi*2+1]);
        }
    }
    __syncthreads();
    if (tid < 128)
        g_invl[(size_t)bh * S_ + qt*128 + tid] = 1.0f / rowSum[tid];

    // ---- context write (scaled by 1/l), permuted to [b][s][h*64+d] ----
    #pragma unroll
    for (int mi = 0; mi < 2; mi++) {
        const int r0 = wm2*32 + mi*16 + gr;
        const float s0 = 1.0f / rowSum[r0];
        const float s1 = 1.0f / rowSum[r0 + 8];
        #pragma unroll
        for (int f = 0; f < 2; f++) {
            const int d = wn2*16 + f*8 + 2*tg;
            size_t d0 = ((size_t)(b*S_ + qt*128 + r0    )) * DM_ + h*DK_ + d;
            size_t d1 = ((size_t)(b*S_ + qt*128 + r0 + 8)) * DM_ + h*DK_ + d;
            *(float2*)&g_Ctx[d0] = make_float2(cacc[mi][f][0]*s0, cacc[mi][f][1]*s0);
            *(float2*)&g_Ctx[d1] = make_float2(cacc[mi][f][2]*s1, cacc[mi][f][3]*s1);
        }
    }
}

// ---------------------------------------------------------------------------
// Normalize attention rows: attn[row][:] *= invl[row]
// ---------------------------------------------------------------------------
__global__ __launch_bounds__(256) void rescale(float* __restrict__ attn)
{
    const int row = blockIdx.x;
    const float s = g_invl[row];
    float4* p = (float4*)(attn + (size_t)row * S_);
    const int t = threadIdx.x;
    float4 v0 = p[t], v1 = p[t + 256];
    v0.x *= s; v0.y *= s; v0.z *= s; v0.w *= s;
    v1.x *= s; v1.y *= s; v1.z *= s; v1.w *= s;
    p[t] = v0; p[t + 256] = v1;
}

// ---------------------------------------------------------------------------
extern "C" void kernel_launch(void* const* d_in, const int* in_sizes, int n_in,
                              void* d_out, int out_size)
{
    const float* q    = (const float*)d_in[0];
    const float* k    = (const float*)d_in[1];
    const float* v    = (const float*)d_in[2];
    const int*   mask = (const int*)  d_in[3];
    const float* Wq   = (const float*)d_in[4];
    const float* Wk   = (const float*)d_in[5];
    const float* Wv   = (const float*)d_in[6];
    const float* Wo   = (const float*)d_in[7];
    const float* bo   = (const float*)d_in[8];

    float* out      = (float*)d_out;
    float* ctx_out  = out;                             // [B,S,DM]
    float* attn_out = out + (size_t)B_ * S_ * DM_;     // [B,H,S,S]

    void *pQ, *pK, *pV, *pC;
    cudaGetSymbolAddress(&pQ, g_Qh);
    cudaGetSymbolAddress(&pK, g_Kh);
    cudaGetSymbolAddress(&pV, g_Vh);
    cudaGetSymbolAddress(&pC, g_Ctx);

    const int smemBytes = SM_WORDS * 4;   // 174592
    cudaFuncSetAttribute(attn_mma, cudaFuncAttributeMaxDynamicSharedMemorySize, smemBytes);

    pack_mask<<<(B_*S_*(S_/32))/8, 256>>>(mask);

    dim3 gproj(M_/128, DM_/128);
    proj_mma<<<gproj, 256>>>(q, Wq, nullptr, (float*)pQ, 1);
    proj_mma<<<gproj, 256>>>(k, Wk, nullptr, (float*)pK, 1);
    proj_mma<<<gproj, 256>>>(v, Wv, nullptr, (float*)pV, 1);

    attn_mma<<<dim3(S_/128, B_*H_), 512, smemBytes>>>(attn_out);

    rescale<<<B_*H_*S_, 256>>>(attn_out);

    proj_mma<<<gproj, 256>>>((const float*)pC, Wo, bo, ctx_out, 0);
}